// round 14
// baseline (speedup 1.0000x reference)
#include <cuda_runtime.h>
#include <cuda_bf16.h>
#include <math.h>
#include <stdint.h>

// ---------------------------------------------------------------------------
// ALiBi self-attention. B=2, T=2048, D=1024, H=16, hd=64.
// sm_100 baseline: mma.sync m16n8k16 bf16 + ldmatrix + cp.async.
//  * GEMMs at mma.sync HMMA ceiling (~255 TF/s measured) — unchanged.
//  * attn5: zero-region attn stores FRONT-LOADED (fire-and-forget before any
//    compute) so the 480MB zero stream overlaps QK/softmax/PV; band-only
//    stores after softmax. P->P3 hi/lo split fused into PV epilogue.
// ---------------------------------------------------------------------------

#define B_    2
#define T_    2048
#define D_    1024
#define H_    16
#define HD_   64
#define MROWS 4096
#define KE    3072
#define NCH   48
#define OUT_ELEMS  ((size_t)MROWS * D_)
#define ATTN_ELEMS ((size_t)B_ * H_ * T_ * T_)
#define WBACK 192

// ---------------- device scratch (allocation-free rule) --------------------
__device__ __align__(256) float g_Q[MROWS * D_];
__device__ __align__(256) float g_K[MROWS * D_];
__device__ __align__(256) float g_V[MROWS * D_];
__device__ __align__(256) __nv_bfloat16 g_A3[(size_t)MROWS * KE];
__device__ __align__(256) __nv_bfloat16 g_P3[(size_t)MROWS * KE];
__device__ __align__(256) __nv_bfloat16 g_W3[4][(size_t)D_ * KE];

// ---------------- PTX helpers ----------------------------------------------
__device__ __forceinline__ uint32_t s2u(const void* p) {
    uint32_t a;
    asm("{ .reg .u64 t; cvta.to.shared.u64 t, %1; cvt.u32.u64 %0, t; }"
        : "=r"(a) : "l"(p));
    return a;
}
__device__ __forceinline__ void cp16(uint32_t dst, const void* src) {
    asm volatile("cp.async.cg.shared.global [%0], [%1], 16;"
                 :: "r"(dst), "l"(src) : "memory");
}
#define CP_COMMIT() asm volatile("cp.async.commit_group;" ::: "memory")
#define CP_WAIT(n)  asm volatile("cp.async.wait_group %0;" :: "n"(n) : "memory")

__device__ __forceinline__ void ldsm4(uint32_t* r, uint32_t addr) {
    asm volatile("ldmatrix.sync.aligned.m8n8.x4.shared.b16 {%0,%1,%2,%3}, [%4];"
                 : "=r"(r[0]), "=r"(r[1]), "=r"(r[2]), "=r"(r[3]) : "r"(addr));
}
__device__ __forceinline__ void mma16816(float* c, const uint32_t* a,
                                         uint32_t b0, uint32_t b1) {
    asm volatile(
        "mma.sync.aligned.m16n8k16.row.col.f32.bf16.bf16.f32 "
        "{%0,%1,%2,%3}, {%4,%5,%6,%7}, {%8,%9}, {%0,%1,%2,%3};"
        : "+f"(c[0]), "+f"(c[1]), "+f"(c[2]), "+f"(c[3])
        : "r"(a[0]), "r"(a[1]), "r"(a[2]), "r"(a[3]), "r"(b0), "r"(b1));
}

// ---------------------------------------------------------------------------
// hi/lo split kernels: fp32 [rows,1024] -> bf16 [rows,3072]
// ---------------------------------------------------------------------------
__device__ __forceinline__ void split_store(const float* __restrict__ in,
                                            __nv_bfloat16* __restrict__ out,
                                            int i, int loMask) {
    float4 v = ((const float4*)in)[i];
    __nv_bfloat162 h01 = __floats2bfloat162_rn(v.x, v.y);
    __nv_bfloat162 h23 = __floats2bfloat162_rn(v.z, v.w);
    __nv_bfloat162 l01 = __floats2bfloat162_rn(v.x - __bfloat162float(h01.x),
                                               v.y - __bfloat162float(h01.y));
    __nv_bfloat162 l23 = __floats2bfloat162_rn(v.z - __bfloat162float(h23.x),
                                               v.w - __bfloat162float(h23.y));
    uint32_t h0 = *(uint32_t*)&h01, h1 = *(uint32_t*)&h23;
    uint32_t l0 = *(uint32_t*)&l01, l1 = *(uint32_t*)&l23;
    int idx = i * 4;
    int r = idx >> 10, k = idx & 1023;
    uint32_t* o = (uint32_t*)(out + (size_t)r * KE + k);
    o[0]    = (loMask & 1) ? l0 : h0;  o[1]    = (loMask & 1) ? l1 : h1;
    o[512]  = (loMask & 2) ? l0 : h0;  o[513]  = (loMask & 2) ? l1 : h1;
    o[1024] = (loMask & 4) ? l0 : h0;  o[1025] = (loMask & 4) ? l1 : h1;
}

__global__ void __launch_bounds__(256) cvt3v(const float* __restrict__ in,
                                             __nv_bfloat16* __restrict__ out,
                                             int n4, int loMask) {
    int i = blockIdx.x * 256 + threadIdx.x;
    if (i < n4) split_store(in, out, i, loMask);
}

__global__ void __launch_bounds__(256) cvtW(const float* __restrict__ w0,
                                            const float* __restrict__ w1,
                                            const float* __restrict__ w2,
                                            const float* __restrict__ w3,
                                            __nv_bfloat16* __restrict__ outBase,
                                            int n4) {
    int i = blockIdx.x * 256 + threadIdx.x;
    if (i >= n4) return;
    int m = blockIdx.y;
    const float* in = (m == 0) ? w0 : (m == 1) ? w1 : (m == 2) ? w2 : w3;
    split_store(in, outBase + (size_t)m * D_ * KE, i, 2);
}

// ---------------------------------------------------------------------------
// HMMA bf16 GEMM, CTA 256x128, 8 warps (4x2), warp tile 64x64,
// 3-stage cp.async pipeline, 256 threads, 1 CTA/SM. (at HMMA ceiling)
// ---------------------------------------------------------------------------
#define ROWB     144
#define TILEA    (256 * ROWB)          // 36864
#define TILEBB   (128 * ROWB)          // 18432
#define STAGEB   (TILEA + TILEBB)      // 55296
#define GSMEM    (3 * STAGEB)          // 165888

__global__ void __launch_bounds__(256, 1) gemm_hmma(
    const __nv_bfloat16* __restrict__ A3, const __nv_bfloat16* __restrict__ B3,
    const float* __restrict__ bias0, const float* __restrict__ bias1,
    const float* __restrict__ bias2,
    float* __restrict__ out0, float* __restrict__ out1, float* __restrict__ out2) {
    extern __shared__ __align__(128) char smem[];
    const uint32_t sb = s2u(smem);
    const int tid  = threadIdx.x;
    const int lane = tid & 31;
    const int w    = tid >> 5;
    const int wm   = (w & 3) * 64;           // M: 4 warps x 64 = 256
    const int wn   = (w >> 2) * 64;          // N: 2 warps x 64 = 128
    const int bm   = blockIdx.y * 256;
    const int bn   = blockIdx.x * 128;

    const int mat = bn >> 10;
    const float* bias = (mat == 0) ? bias0 : (mat == 1) ? bias1 : bias2;
    float* C          = (mat == 0) ? out0  : (mat == 1) ? out1  : out2;
    const int cn = bn & 1023;

    float acc[4][8][4];
#pragma unroll
    for (int i = 0; i < 4; i++)
#pragma unroll
        for (int j = 0; j < 8; j++)
#pragma unroll
            for (int q = 0; q < 4; q++) acc[i][j][q] = 0.f;

    const char* gAbase = (const char*)A3 + (size_t)bm * (KE * 2);
    const char* gBbase = (const char*)B3 + (size_t)bn * (KE * 2);

#define LOAD_STAGE(c, s)                                                      \
    do {                                                                      \
        uint32_t dA = sb + (s) * STAGEB;                                      \
        uint32_t dB = dA + TILEA;                                             \
        const char* sA = gAbase + (c) * 128;                                  \
        const char* sB = gBbase + (c) * 128;                                  \
        _Pragma("unroll")                                                     \
        for (int it = 0; it < 8; it++) {                                      \
            int u = tid + it * 256;      /* A: 2048 16B units */              \
            int r = u >> 3, q = (u & 7) << 4;                                 \
            cp16(dA + r * ROWB + q, sA + (size_t)r * (KE * 2) + q);           \
        }                                                                     \
        _Pragma("unroll")                                                     \
        for (int it = 0; it < 4; it++) {                                      \
            int u = tid + it * 256;      /* B: 1024 16B units */              \
            int r = u >> 3, q = (u & 7) << 4;                                 \
            cp16(dB + r * ROWB + q, sB + (size_t)r * (KE * 2) + q);           \
        }                                                                     \
        CP_COMMIT();                                                          \
    } while (0)

    LOAD_STAGE(0, 0);
    LOAD_STAGE(1, 1);

    for (int c = 0; c < NCH; c++) {
        const int s = c - (c / 3) * 3;            // c % 3
        if (c + 1 < NCH) CP_WAIT(1); else CP_WAIT(0);
        __syncthreads();
        if (c + 2 < NCH) {
            int s2 = (c + 2) - ((c + 2) / 3) * 3;
            LOAD_STAGE(c + 2, s2);
        }

        const uint32_t aBase = sb + s * STAGEB +
                               (wm + (lane & 15)) * ROWB + ((lane >> 4) << 4);
        const uint32_t bBase = sb + s * STAGEB + TILEA +
                               (wn + (lane & 15)) * ROWB + ((lane >> 4) << 4);
#pragma unroll
        for (int kk = 0; kk < 4; kk++) {
            uint32_t af[4][4], bf[4][4];
#pragma unroll
            for (int i = 0; i < 4; i++)
                ldsm4(af[i], aBase + i * 16 * ROWB + kk * 32);
#pragma unroll
            for (int p = 0; p < 4; p++)
                ldsm4(bf[p], bBase + p * 16 * ROWB + kk * 32);
#pragma unroll
            for (int i = 0; i < 4; i++)
#pragma unroll
                for (int j = 0; j < 8; j++)
                    mma16816(acc[i][j], af[i], bf[j >> 1][j & 1],
                             bf[j >> 1][(j & 1) + 2]);
        }
    }

    const int g = lane >> 2, tg = lane & 3;
#pragma unroll
    for (int i = 0; i < 4; i++) {
#pragma unroll
        for (int j = 0; j < 8; j++) {
            int col  = cn + wn + j * 8 + tg * 2;
            float b0 = bias[col], b1 = bias[col + 1];
            int row0 = bm + wm + i * 16 + g;
            float2 v0 = make_float2(acc[i][j][0] + b0, acc[i][j][1] + b1);
            float2 v1 = make_float2(acc[i][j][2] + b0, acc[i][j][3] + b1);
            *(float2*)&C[(size_t)row0 * D_ + col]       = v0;
            *(float2*)&C[(size_t)(row0 + 8) * D_ + col] = v1;
        }
    }
}

// ---------------------------------------------------------------------------
// attn5: banded attention. Zero-region attn stores issued FIRST (overlap with
// all compute); band-only stores after softmax. float4 LDS + xor swizzle.
// ---------------------------------------------------------------------------
#define QSS 68
#define KSS 68
#define SCS 232
#define QS_OFF 0
#define KS_OFF (32 * QSS)                   // 2176
#define SC_OFF (KS_OFF + 128 * KSS)         // 10880
#define ASMEM  ((SC_OFF + 32 * SCS) * 4)    // 73216 B
#define SWZ(r) ((((r) >> 2) & 7) << 2)

__global__ void __launch_bounds__(256) attn5(
    const float* __restrict__ Q, const float* __restrict__ K,
    const float* __restrict__ V, __nv_bfloat16* __restrict__ P3,
    float* __restrict__ attn_out, int has_attn) {
    extern __shared__ float sm[];
    float* Qs = sm + QS_OFF;
    float* Ks = sm + KS_OFF;
    float* Sc = sm + SC_OFF;

    const int b = blockIdx.z, h = blockIdx.y;
    const int q0 = blockIdx.x * 32;
    const int tid = threadIdx.x;
    const int jlo = (q0 > WBACK) ? q0 - WBACK : 0;
    const int nk = q0 + 32 - jlo;               // mult of 32, <= 224
    const size_t bT = (size_t)b * T_;
    const int qr = tid >> 3, l8 = tid & 7;
    const int swr = SWZ(qr);
    const int iq = q0 + qr;

    // ---- FRONT-LOADED zero stores: [0,jlo) and [q0+32,T) of each row.
    //      Fire-and-forget; drains in DRAM while we compute below.
    float4* myrow4 = (float4*)(attn_out + ((size_t)(b * H_ + h) * T_ + iq) * T_);
    if (has_attn) {
        const float4 z = make_float4(0.f, 0.f, 0.f, 0.f);
        const int zr1 = jlo >> 2;               // mult of 8 (or 0)
        const int z2s = (q0 + 32) >> 2;         // mult of 8
        const int zr2 = (T_ >> 2) - z2s;
        for (int c = l8; c < zr1; c += 8) myrow4[c] = z;
        for (int c = l8; c < zr2; c += 8) myrow4[z2s + c] = z;
    }

    // ---- Q tile 32x64, float4 rows with swizzle
#pragma unroll
    for (int i = 0; i < 2; i++) {
        int u = i * 256 + tid;
        int row = u >> 4, cu = (u & 15) << 2;
        float4 v = *(const float4*)(Q + (bT + q0 + row) * D_ + h * HD_ + cu);
        *(float4*)&Qs[row * QSS + (cu ^ SWZ(row))] = v;
    }

    // ---- QK: 4q x 4k per thread, float4 over d
    const int kg = tid >> 3, qg = tid & 7;
    const int swq = qg << 2;                    // SWZ(4qg+i) for i<4
    for (int base = 0; base < nk; base += 128) {
        const int csize = (nk - base < 128) ? nk - base : 128;
        __syncthreads();
#pragma unroll
        for (int i = 0; i < 8; i++) {
            int u = i * 256 + tid;
            int row = u >> 4, cu = (u & 15) << 2;
            if (row < csize) {
                float4 v = *(const float4*)(K + (bT + jlo + base + row) * D_ +
                                            h * HD_ + cu);
                *(float4*)&Ks[row * KSS + (cu ^ SWZ(row))] = v;
            }
        }
        __syncthreads();
        if (4 * kg < csize) {
            const int swk = (kg & 7) << 2;      // SWZ(4kg+j) for j<4
            float acc[4][4];
#pragma unroll
            for (int i = 0; i < 4; i++)
#pragma unroll
                for (int j = 0; j < 4; j++) acc[i][j] = 0.f;
#pragma unroll
            for (int d4 = 0; d4 < 16; d4++) {
                const int dof = d4 << 2;
                float4 qv[4], kv[4];
#pragma unroll
                for (int i = 0; i < 4; i++)
                    qv[i] = *(const float4*)&Qs[(4 * qg + i) * QSS + (dof ^ swq)];
#pragma unroll
                for (int j = 0; j < 4; j++)
                    kv[j] = *(const float4*)&Ks[(4 * kg + j) * KSS + (dof ^ swk)];
#pragma unroll
                for (int i = 0; i < 4; i++)
#pragma unroll
                    for (int j = 0; j < 4; j++)
                        acc[i][j] += qv[i].x * kv[j].x + qv[i].y * kv[j].y +
                                     qv[i].z * kv[j].z + qv[i].w * kv[j].w;
            }
#pragma unroll
            for (int i = 0; i < 4; i++) {
                float4 sv = make_float4(acc[i][0] * 0.125f, acc[i][1] * 0.125f,
                                        acc[i][2] * 0.125f, acc[i][3] * 0.125f);
                *(float4*)&Sc[(4 * qg + i) * SCS + ((base + 4 * kg) ^ swq)] = sv;
            }
        }
    }
    __syncthreads();

    // ---- softmax per query row (8 lanes/row), swizzled scalar access
    float m = -1e30f;
    for (int idx = l8; idx < nk; idx += 8) {
        int j = jlo + idx;
        int ph = qr * SCS + (idx ^ swr);
        float sv = (j <= iq) ? (Sc[ph] - (float)(iq - j)) : -1e30f;
        Sc[ph] = sv;
        m = fmaxf(m, sv);
    }
#pragma unroll
    for (int o = 4; o >= 1; o >>= 1)
        m = fmaxf(m, __shfl_xor_sync(0xffffffffu, m, o, 8));
    float sum = 0.f;
    for (int idx = l8; idx < nk; idx += 8) {
        int ph = qr * SCS + (idx ^ swr);
        float sv = Sc[ph];
        float e = (sv > -1e29f) ? expf(sv - m) : 0.f;
        Sc[ph] = e;
        sum += e;
    }
#pragma unroll
    for (int o = 4; o >= 1; o >>= 1)
        sum += __shfl_xor_sync(0xffffffffu, sum, o, 8);
    float inv = 1.f / sum;
    for (int idx = l8; idx < nk; idx += 8)
        Sc[qr * SCS + (idx ^ swr)] *= inv;
    __syncthreads();

    // ---- band-only attn store: j4 in [jlo/4, (q0+32)/4), causal zeros inside
    if (has_attn) {
        const int j4lo = jlo >> 2, j4hi = (q0 + 32) >> 2;
        for (int j4 = j4lo + l8; j4 < j4hi; j4 += 8) {
            int j = j4 * 4;
            int lo0 = j - jlo;                  // >= 0, mult of 4
            float4 v;
            v.x = (j + 0 <= iq) ? Sc[qr * SCS + ((lo0 + 0) ^ swr)] : 0.f;
            v.y = (j + 1 <= iq) ? Sc[qr * SCS + ((lo0 + 1) ^ swr)] : 0.f;
            v.z = (j + 2 <= iq) ? Sc[qr * SCS + ((lo0 + 2) ^ swr)] : 0.f;
            v.w = (j + 3 <= iq) ? Sc[qr * SCS + ((lo0 + 3) ^ swr)] : 0.f;
            myrow4[j4] = v;
        }
    }

    // ---- PV: 4q x 4d per thread, key-halves, float4 wv (over jj) + vv (over d)
    const int hf = tid >> 7, pg = (tid >> 4) & 7, dg = tid & 15;
    const int swp = pg << 2;                    // SWZ(4pg+i)
    const int dof = dg << 2;
    float4 pacc[4];
#pragma unroll
    for (int i = 0; i < 4; i++) pacc[i] = make_float4(0.f, 0.f, 0.f, 0.f);

    for (int base = 0; base < nk; base += 128) {
        const int csize = (nk - base < 128) ? nk - base : 128;
        __syncthreads();
#pragma unroll
        for (int i = 0; i < 8; i++) {
            int u = i * 256 + tid;
            int row = u >> 4, cu = (u & 15) << 2;
            if (row < csize) {
                float4 v = *(const float4*)(V + (bT + jlo + base + row) * D_ +
                                            h * HD_ + cu);
                *(float4*)&Ks[row * KSS + (cu ^ SWZ(row))] = v;
            }
        }
        __syncthreads();
        const int half = csize >> 1;            // mult of 16
        const int j0 = hf * half, j1 = j0 + half;
        for (int jj = j0; jj < j1; jj += 4) {
            const int swv = SWZ(jj);            // same for jj..jj+3
            float4 wv[4], vv[4];
#pragma unroll
            for (int i = 0; i < 4; i++)
                wv[i] = *(const float4*)&Sc[(4 * pg + i) * SCS + ((base + jj) ^ swp)];
#pragma unroll
            for (int r = 0; r < 4; r++)
                vv[r] = *(const float4*)&Ks[(jj + r) * KSS + (dof ^ swv)];
#pragma unroll
            for (int i = 0; i < 4; i++) {
                pacc[i].x += wv[i].x * vv[0].x + wv[i].y * vv[1].x +
                             wv[i].z * vv[2].x + wv[i].w * vv[3].x;
                pacc[i].y += wv[i].x * vv[0].y + wv[i].y * vv[1].y +
                             wv[i].z * vv[2].y + wv[i].w * vv[3].y;
                pacc[i].z += wv[i].x * vv[0].z + wv[i].y * vv[1].z +
                             wv[i].z * vv[2].z + wv[i].w * vv[3].z;
                pacc[i].w += wv[i].x * vv[0].w + wv[i].y * vv[1].w +
                             wv[i].z * vv[2].w + wv[i].w * vv[3].w;
            }
        }
    }
    __syncthreads();

    // ---- reduce halves via Qs, write P3 hi|hi|lo (4 bf16 = 8B per segment)
    if (hf == 0) {
#pragma unroll
        for (int i = 0; i < 4; i++)
            *(float4*)&Qs[(4 * pg + i) * QSS + (dof ^ swp)] = pacc[i];
    }
    __syncthreads();
    if (hf == 1) {
#pragma unroll
        for (int i = 0; i < 4; i++) {
            float4 o = *(const float4*)&Qs[(4 * pg + i) * QSS + (dof ^ swp)];
            float4 v = make_float4(pacc[i].x + o.x, pacc[i].y + o.y,
                                   pacc[i].z + o.z, pacc[i].w + o.w);
            __nv_bfloat162 hA = __floats2bfloat162_rn(v.x, v.y);
            __nv_bfloat162 hB = __floats2bfloat162_rn(v.z, v.w);
            __nv_bfloat162 lA = __floats2bfloat162_rn(v.x - __bfloat162float(hA.x),
                                                      v.y - __bfloat162float(hA.y));
            __nv_bfloat162 lB = __floats2bfloat162_rn(v.z - __bfloat162float(hB.x),
                                                      v.w - __bfloat162float(hB.y));
            uint2 hw = make_uint2(*(uint32_t*)&hA, *(uint32_t*)&hB);
            uint2 lw = make_uint2(*(uint32_t*)&lA, *(uint32_t*)&lB);
            __nv_bfloat16* p = P3 + (bT + q0 + 4 * pg + i) * KE + h * HD_ + dof;
            *(uint2*)(p)        = hw;
            *(uint2*)(p + 1024) = hw;
            *(uint2*)(p + 2048) = lw;
        }
    }
}

// ---------------------------------------------------------------------------
extern "C" void kernel_launch(void* const* d_in, const int* in_sizes, int n_in,
                              void* d_out, int out_size) {
    const float* x  = (const float*)d_in[0];
    const float* Wq = (const float*)d_in[1];
    const float* bq = (const float*)d_in[2];
    const float* Wk = (const float*)d_in[3];
    const float* bk = (const float*)d_in[4];
    const float* Wv = (const float*)d_in[5];
    const float* bv = (const float*)d_in[6];
    const float* Wo = (const float*)d_in[7];
    const float* bo = (const float*)d_in[8];
    float* out = (float*)d_out;

    const int has_attn = ((size_t)out_size >= OUT_ELEMS + ATTN_ELEMS) ? 1 : 0;

    float *pQ, *pK, *pV;
    __nv_bfloat16 *pA3, *pP3, *pW3;
    cudaGetSymbolAddress((void**)&pQ, g_Q);
    cudaGetSymbolAddress((void**)&pK, g_K);
    cudaGetSymbolAddress((void**)&pV, g_V);
    cudaGetSymbolAddress((void**)&pA3, g_A3);
    cudaGetSymbolAddress((void**)&pP3, g_P3);
    cudaGetSymbolAddress((void**)&pW3, g_W3);

    cudaFuncSetAttribute(gemm_hmma, cudaFuncAttributeMaxDynamicSharedMemorySize,
                         GSMEM);
    cudaFuncSetAttribute(attn5, cudaFuncAttributeMaxDynamicSharedMemorySize,
                         ASMEM);

    const int nA4 = MROWS * D_ / 4;
    const int nW4 = D_ * D_ / 4;
    cvt3v<<<(nA4 + 255) / 256, 256>>>(x, pA3, nA4, 4);        // [h|h|l]
    dim3 wg((nW4 + 255) / 256, 4);
    cvtW<<<wg, 256>>>(Wq, Wk, Wv, Wo, pW3, nW4);              // [h|l|h] x4

    dim3 gqkv(3 * D_ / 128, MROWS / 256);   // (24, 16)
    gemm_hmma<<<gqkv, 256, GSMEM>>>(pA3, pW3, bq, bk, bv, pQ, pK, pV);

    dim3 agrid(T_ / 32, H_, B_);            // (64, 16, 2)
    attn5<<<agrid, 256, ASMEM>>>(pQ, pK, pV, pP3,
                                 has_attn ? (out + OUT_ELEMS) : out, has_attn);

    dim3 go(D_ / 128, MROWS / 256);         // (8, 16)
    gemm_hmma<<<go, 256, GSMEM>>>(pP3, pW3 + 3 * (size_t)D_ * KE,
                                  bo, bo, bo, out, out, out);
}

// round 15
// speedup vs baseline: 1.0733x; 1.0733x over previous
#include <cuda_runtime.h>
#include <cuda_bf16.h>
#include <math.h>
#include <stdint.h>

// ---------------------------------------------------------------------------
// ALiBi self-attention. B=2, T=2048, D=1024, H=16, hd=64.
// sm_100 baseline: mma.sync m16n8k16 bf16 + ldmatrix + cp.async.
//  * GEMMs: R10 config (128x128 CTA, 64x64 warp tiles, 3-stage, 2 CTA/SM).
//  * attn6: QK on TENSOR pipe (bf16 hi/lo 3-term, hd 64->192, HMMA) --
//    attention measured FMA-pipe bound (32 TF/s ceiling); tensor pipe idle.
//    Softmax/store/PV/P3-epilogue carried from validated attn4.
// ---------------------------------------------------------------------------

#define B_    2
#define T_    2048
#define D_    1024
#define H_    16
#define HD_   64
#define MROWS 4096
#define KE    3072
#define NCH   48
#define OUT_ELEMS  ((size_t)MROWS * D_)
#define ATTN_ELEMS ((size_t)B_ * H_ * T_ * T_)
#define WBACK 192

// ---------------- device scratch (allocation-free rule) --------------------
__device__ __align__(256) float g_Q[MROWS * D_];
__device__ __align__(256) float g_K[MROWS * D_];
__device__ __align__(256) float g_V[MROWS * D_];
__device__ __align__(256) __nv_bfloat16 g_A3[(size_t)MROWS * KE];
__device__ __align__(256) __nv_bfloat16 g_P3[(size_t)MROWS * KE];
__device__ __align__(256) __nv_bfloat16 g_W3[4][(size_t)D_ * KE];

// ---------------- PTX helpers ----------------------------------------------
__device__ __forceinline__ uint32_t s2u(const void* p) {
    uint32_t a;
    asm("{ .reg .u64 t; cvta.to.shared.u64 t, %1; cvt.u32.u64 %0, t; }"
        : "=r"(a) : "l"(p));
    return a;
}
__device__ __forceinline__ void cp16(uint32_t dst, const void* src) {
    asm volatile("cp.async.cg.shared.global [%0], [%1], 16;"
                 :: "r"(dst), "l"(src) : "memory");
}
#define CP_COMMIT() asm volatile("cp.async.commit_group;" ::: "memory")
#define CP_WAIT(n)  asm volatile("cp.async.wait_group %0;" :: "n"(n) : "memory")

__device__ __forceinline__ void ldsm4(uint32_t* r, uint32_t addr) {
    asm volatile("ldmatrix.sync.aligned.m8n8.x4.shared.b16 {%0,%1,%2,%3}, [%4];"
                 : "=r"(r[0]), "=r"(r[1]), "=r"(r[2]), "=r"(r[3]) : "r"(addr));
}
__device__ __forceinline__ void mma16816(float* c, const uint32_t* a,
                                         uint32_t b0, uint32_t b1) {
    asm volatile(
        "mma.sync.aligned.m16n8k16.row.col.f32.bf16.bf16.f32 "
        "{%0,%1,%2,%3}, {%4,%5,%6,%7}, {%8,%9}, {%0,%1,%2,%3};"
        : "+f"(c[0]), "+f"(c[1]), "+f"(c[2]), "+f"(c[3])
        : "r"(a[0]), "r"(a[1]), "r"(a[2]), "r"(a[3]), "r"(b0), "r"(b1));
}

// ---------------------------------------------------------------------------
// hi/lo split kernels: fp32 [rows,1024] -> bf16 [rows,3072]
// ---------------------------------------------------------------------------
__device__ __forceinline__ void split_store(const float* __restrict__ in,
                                            __nv_bfloat16* __restrict__ out,
                                            int i, int loMask) {
    float4 v = ((const float4*)in)[i];
    __nv_bfloat162 h01 = __floats2bfloat162_rn(v.x, v.y);
    __nv_bfloat162 h23 = __floats2bfloat162_rn(v.z, v.w);
    __nv_bfloat162 l01 = __floats2bfloat162_rn(v.x - __bfloat162float(h01.x),
                                               v.y - __bfloat162float(h01.y));
    __nv_bfloat162 l23 = __floats2bfloat162_rn(v.z - __bfloat162float(h23.x),
                                               v.w - __bfloat162float(h23.y));
    uint32_t h0 = *(uint32_t*)&h01, h1 = *(uint32_t*)&h23;
    uint32_t l0 = *(uint32_t*)&l01, l1 = *(uint32_t*)&l23;
    int idx = i * 4;
    int r = idx >> 10, k = idx & 1023;
    uint32_t* o = (uint32_t*)(out + (size_t)r * KE + k);
    o[0]    = (loMask & 1) ? l0 : h0;  o[1]    = (loMask & 1) ? l1 : h1;
    o[512]  = (loMask & 2) ? l0 : h0;  o[513]  = (loMask & 2) ? l1 : h1;
    o[1024] = (loMask & 4) ? l0 : h0;  o[1025] = (loMask & 4) ? l1 : h1;
}

__global__ void __launch_bounds__(256) cvt3v(const float* __restrict__ in,
                                             __nv_bfloat16* __restrict__ out,
                                             int n4, int loMask) {
    int i = blockIdx.x * 256 + threadIdx.x;
    if (i < n4) split_store(in, out, i, loMask);
}

__global__ void __launch_bounds__(256) cvtW(const float* __restrict__ w0,
                                            const float* __restrict__ w1,
                                            const float* __restrict__ w2,
                                            const float* __restrict__ w3,
                                            __nv_bfloat16* __restrict__ outBase,
                                            int n4) {
    int i = blockIdx.x * 256 + threadIdx.x;
    if (i >= n4) return;
    int m = blockIdx.y;
    const float* in = (m == 0) ? w0 : (m == 1) ? w1 : (m == 2) ? w2 : w3;
    split_store(in, outBase + (size_t)m * D_ * KE, i, 2);
}

// ---------------------------------------------------------------------------
// HMMA bf16 GEMM (R10 config): CTA 128x128, 4 warps (2x2), warp tile 64x64,
// 3-stage cp.async, 128 threads, 2 CTAs/SM.
// ---------------------------------------------------------------------------
#define ROWB     144
#define TILEB    (128 * ROWB)
#define STAGEB   (2 * TILEB)          // 36864
#define GSMEM    (3 * STAGEB)         // 110592

__global__ void __launch_bounds__(128, 2) gemm_hmma(
    const __nv_bfloat16* __restrict__ A3, const __nv_bfloat16* __restrict__ B3,
    const float* __restrict__ bias0, const float* __restrict__ bias1,
    const float* __restrict__ bias2,
    float* __restrict__ out0, float* __restrict__ out1, float* __restrict__ out2) {
    extern __shared__ __align__(128) char smem[];
    const uint32_t sb = s2u(smem);
    const int tid  = threadIdx.x;
    const int lane = tid & 31;
    const int w    = tid >> 5;
    const int wm   = (w & 1) * 64;
    const int wn   = (w >> 1) * 64;
    const int bm   = blockIdx.y * 128;
    const int bn   = blockIdx.x * 128;

    const int mat = bn >> 10;
    const float* bias = (mat == 0) ? bias0 : (mat == 1) ? bias1 : bias2;
    float* C          = (mat == 0) ? out0  : (mat == 1) ? out1  : out2;
    const int cn = bn & 1023;

    float acc[4][8][4];
#pragma unroll
    for (int i = 0; i < 4; i++)
#pragma unroll
        for (int j = 0; j < 8; j++)
#pragma unroll
            for (int q = 0; q < 4; q++) acc[i][j][q] = 0.f;

    const char* gAbase = (const char*)A3 + (size_t)bm * (KE * 2);
    const char* gBbase = (const char*)B3 + (size_t)bn * (KE * 2);

#define LOAD_STAGE(c, s)                                                      \
    do {                                                                      \
        uint32_t dA = sb + (s) * STAGEB;                                      \
        uint32_t dB = dA + TILEB;                                             \
        const char* sA = gAbase + (c) * 128;                                  \
        const char* sB = gBbase + (c) * 128;                                  \
        _Pragma("unroll")                                                     \
        for (int it = 0; it < 8; it++) {                                      \
            int u = tid + it * 128;                                           \
            int r = u >> 3, q = (u & 7) << 4;                                 \
            cp16(dA + r * ROWB + q, sA + (size_t)r * (KE * 2) + q);           \
            cp16(dB + r * ROWB + q, sB + (size_t)r * (KE * 2) + q);           \
        }                                                                     \
        CP_COMMIT();                                                          \
    } while (0)

    LOAD_STAGE(0, 0);
    LOAD_STAGE(1, 1);

    for (int c = 0; c < NCH; c++) {
        const int s = c - (c / 3) * 3;            // c % 3
        if (c + 1 < NCH) CP_WAIT(1); else CP_WAIT(0);
        __syncthreads();
        if (c + 2 < NCH) {
            int s2 = (c + 2) - ((c + 2) / 3) * 3;
            LOAD_STAGE(c + 2, s2);
        }

        const uint32_t aBase = sb + s * STAGEB +
                               (wm + (lane & 15)) * ROWB + ((lane >> 4) << 4);
        const uint32_t bBase = sb + s * STAGEB + TILEB +
                               (wn + (lane & 15)) * ROWB + ((lane >> 4) << 4);
#pragma unroll
        for (int kk = 0; kk < 4; kk++) {
            uint32_t af[4][4], bf[4][4];
#pragma unroll
            for (int i = 0; i < 4; i++)
                ldsm4(af[i], aBase + i * 16 * ROWB + kk * 32);
#pragma unroll
            for (int p = 0; p < 4; p++)
                ldsm4(bf[p], bBase + p * 16 * ROWB + kk * 32);
#pragma unroll
            for (int i = 0; i < 4; i++)
#pragma unroll
                for (int j = 0; j < 8; j++)
                    mma16816(acc[i][j], af[i], bf[j >> 1][j & 1],
                             bf[j >> 1][(j & 1) + 2]);
        }
    }

    const int g = lane >> 2, tg = lane & 3;
#pragma unroll
    for (int i = 0; i < 4; i++) {
#pragma unroll
        for (int j = 0; j < 8; j++) {
            int col  = cn + wn + j * 8 + tg * 2;
            float b0 = bias[col], b1 = bias[col + 1];
            int row0 = bm + wm + i * 16 + g;
            float2 v0 = make_float2(acc[i][j][0] + b0, acc[i][j][1] + b1);
            float2 v1 = make_float2(acc[i][j][2] + b0, acc[i][j][3] + b1);
            *(float2*)&C[(size_t)row0 * D_ + col]       = v0;
            *(float2*)&C[(size_t)(row0 + 8) * D_ + col] = v1;
        }
    }
}

// ---------------------------------------------------------------------------
// attn6: QK on tensor pipe. smem (66048 B):
//   union [36864 B]:
//     QK phase: Q3s bf16 3 segs x [32 rows x 128B, SW-swizzled]   (12288 B)
//               K3c bf16 3 segs x [64 rows x 128B, SW-swizzled]   (24576 B)
//     PV phase: Vs float [128][68] (attn4 layout)                 (34816 B)
//     epilogue: staging float [32][68]                            ( 8704 B)
//   Sc float [32][228] at offset 36864                            (29184 B)
// Q3 = [h|h|l], K3 = [h|l|h] along expanded k=192 (3 segs of 64).
// ---------------------------------------------------------------------------
#define SCS2   228
#define SC2_OFF 36864
#define ASMEM6 (SC2_OFF + 32 * SCS2 * 4)    // 66048
#define K3_OFF 12288
#define VSS    68
#define SWZ(r) ((((r) >> 2) & 7) << 2)

__global__ void __launch_bounds__(256) attn6(
    const float* __restrict__ Q, const float* __restrict__ K,
    const float* __restrict__ V, __nv_bfloat16* __restrict__ P3,
    float* __restrict__ attn_out, int has_attn) {
    extern __shared__ __align__(128) char smc[];
    const uint32_t sb = s2u(smc);
    float* smf = (float*)smc;                 // union region (floats)
    float* Sc  = (float*)(smc + SC2_OFF);

    const int b = blockIdx.z, h = blockIdx.y;
    const int q0 = blockIdx.x * 32;
    const int tid = threadIdx.x;
    const int jlo = (q0 > WBACK) ? q0 - WBACK : 0;
    const int nk = q0 + 32 - jlo;             // mult of 32, <= 224
    const size_t bT = (size_t)b * T_;
    const int qr = tid >> 3, l8 = tid & 7;
    const int iq = q0 + qr;

    // ---- Q3 convert: 32x64 fp32 -> 3 bf16 segs (h,h,l), swizzled 128B rows
#pragma unroll
    for (int i = 0; i < 2; i++) {
        int u = i * 256 + tid;
        int row = u >> 4, d4 = (u & 15) << 2;
        float4 v = *(const float4*)(Q + (bT + q0 + row) * D_ + h * HD_ + d4);
        __nv_bfloat162 hA = __floats2bfloat162_rn(v.x, v.y);
        __nv_bfloat162 hB = __floats2bfloat162_rn(v.z, v.w);
        __nv_bfloat162 lA = __floats2bfloat162_rn(v.x - __bfloat162float(hA.x),
                                                  v.y - __bfloat162float(hA.y));
        __nv_bfloat162 lB = __floats2bfloat162_rn(v.z - __bfloat162float(hB.x),
                                                  v.w - __bfloat162float(hB.y));
        uint2 hw = make_uint2(*(uint32_t*)&hA, *(uint32_t*)&hB);
        uint2 lw = make_uint2(*(uint32_t*)&lA, *(uint32_t*)&lB);
        uint32_t off = row * 128 + ((((d4 >> 3) ^ (row & 7))) << 4) + ((d4 & 4) << 1);
        *(uint2*)(smc + 0    + off) = hw;     // seg0: h
        *(uint2*)(smc + 4096 + off) = hw;     // seg1: h
        *(uint2*)(smc + 8192 + off) = lw;     // seg2: l
    }

    const int wid = tid >> 5, lane = tid & 31;
    const int mt = (wid & 1) * 16;            // m-tile (query base)
    const int ng = wid >> 1;                  // n-group (16 keys)

    // ---- QK: keys in chunks of 64, HMMA over expanded k=192
    for (int base = 0; base < nk; base += 64) {
        const int csize = (nk - base < 64) ? nk - base : 64;   // 32 or 64
        __syncthreads();
#pragma unroll
        for (int i = 0; i < 4; i++) {         // K3 convert (h,l,h)
            int u = i * 256 + tid;
            int row = u >> 4, d4 = (u & 15) << 2;
            if (row < csize) {
                float4 v = *(const float4*)(K + (bT + jlo + base + row) * D_ +
                                            h * HD_ + d4);
                __nv_bfloat162 hA = __floats2bfloat162_rn(v.x, v.y);
                __nv_bfloat162 hB = __floats2bfloat162_rn(v.z, v.w);
                __nv_bfloat162 lA = __floats2bfloat162_rn(v.x - __bfloat162float(hA.x),
                                                          v.y - __bfloat162float(hA.y));
                __nv_bfloat162 lB = __floats2bfloat162_rn(v.z - __bfloat162float(hB.x),
                                                          v.w - __bfloat162float(hB.y));
                uint2 hw = make_uint2(*(uint32_t*)&hA, *(uint32_t*)&hB);
                uint2 lw = make_uint2(*(uint32_t*)&lA, *(uint32_t*)&lB);
                uint32_t off = row * 128 + ((((d4 >> 3) ^ (row & 7))) << 4) +
                               ((d4 & 4) << 1);
                *(uint2*)(smc + K3_OFF + 0     + off) = hw;   // seg0: h
                *(uint2*)(smc + K3_OFF + 8192  + off) = lw;   // seg1: l
                *(uint2*)(smc + K3_OFF + 16384 + off) = hw;   // seg2: h
            }
        }
        __syncthreads();
        if (ng * 16 < csize) {
            float acc0[4] = {0.f, 0.f, 0.f, 0.f};
            float acc1[4] = {0.f, 0.f, 0.f, 0.f};
#pragma unroll
            for (int s = 0; s < 3; s++) {
                const uint32_t qb = sb + s * 4096;
                const uint32_t kb = sb + K3_OFF + s * 8192;
#pragma unroll
                for (int ks = 0; ks < 4; ks++) {
                    uint32_t af[4], bf[4];
                    {
                        int r = mt + (lane & 15);
                        int c = ks * 2 + (lane >> 4);
                        ldsm4(af, qb + r * 128 + ((c ^ (r & 7)) << 4));
                    }
                    {
                        int r = ng * 16 + (lane & 15);
                        int c = ks * 2 + (lane >> 4);
                        ldsm4(bf, kb + r * 128 + ((c ^ (r & 7)) << 4));
                    }
                    mma16816(acc0, af, bf[0], bf[2]);   // keys ng*16+0..7
                    mma16816(acc1, af, bf[1], bf[3]);   // keys ng*16+8..15
                }
            }
            const int g = lane >> 2, tg = lane & 3;
            const int r0 = mt + g;
            const int cb = base + ng * 16 + tg * 2;
            Sc[r0 * SCS2 + cb]           = acc0[0] * 0.125f;
            Sc[r0 * SCS2 + cb + 1]       = acc0[1] * 0.125f;
            Sc[(r0 + 8) * SCS2 + cb]     = acc0[2] * 0.125f;
            Sc[(r0 + 8) * SCS2 + cb + 1] = acc0[3] * 0.125f;
            Sc[r0 * SCS2 + cb + 8]           = acc1[0] * 0.125f;
            Sc[r0 * SCS2 + cb + 9]           = acc1[1] * 0.125f;
            Sc[(r0 + 8) * SCS2 + cb + 8]     = acc1[2] * 0.125f;
            Sc[(r0 + 8) * SCS2 + cb + 9]     = acc1[3] * 0.125f;
        }
    }
    __syncthreads();

    // ---- softmax per query row (8 lanes/row)
    float m = -1e30f;
    for (int idx = l8; idx < nk; idx += 8) {
        int j = jlo + idx;
        int ph = qr * SCS2 + idx;
        float sv = (j <= iq) ? (Sc[ph] - (float)(iq - j)) : -1e30f;
        Sc[ph] = sv;
        m = fmaxf(m, sv);
    }
#pragma unroll
    for (int o = 4; o >= 1; o >>= 1)
        m = fmaxf(m, __shfl_xor_sync(0xffffffffu, m, o, 8));
    float sum = 0.f;
    for (int idx = l8; idx < nk; idx += 8) {
        int ph = qr * SCS2 + idx;
        float sv = Sc[ph];
        float e = (sv > -1e29f) ? expf(sv - m) : 0.f;
        Sc[ph] = e;
        sum += e;
    }
#pragma unroll
    for (int o = 4; o >= 1; o >>= 1)
        sum += __shfl_xor_sync(0xffffffffu, sum, o, 8);
    float inv = 1.f / sum;
    for (int idx = l8; idx < nk; idx += 8)
        Sc[qr * SCS2 + idx] *= inv;
    __syncthreads();

    // ---- full attn row (float4, zeros outside band)
    if (has_attn) {
        float* row = attn_out + ((size_t)(b * H_ + h) * T_ + iq) * T_;
        for (int j4 = l8; j4 < T_ / 4; j4 += 8) {
            int j = j4 * 4;
            float4 v = make_float4(0.f, 0.f, 0.f, 0.f);
            if (j + 3 >= jlo && j <= iq) {
                int lo0 = j - jlo;
                v.x = (j + 0 >= jlo && j + 0 <= iq) ? Sc[qr * SCS2 + lo0 + 0] : 0.f;
                v.y = (j + 1 >= jlo && j + 1 <= iq) ? Sc[qr * SCS2 + lo0 + 1] : 0.f;
                v.z = (j + 2 >= jlo && j + 2 <= iq) ? Sc[qr * SCS2 + lo0 + 2] : 0.f;
                v.w = (j + 3 >= jlo && j + 3 <= iq) ? Sc[qr * SCS2 + lo0 + 3] : 0.f;
            }
            *(float4*)(row + j) = v;
        }
    }

    // ---- PV: 4q x 4d per thread, key-halves, float4 (attn4, Vs in union)
    const int hf = tid >> 7, pg = (tid >> 4) & 7, dg = tid & 15;
    const int swp = pg << 2;
    const int dof = dg << 2;
    float4 pacc[4];
#pragma unroll
    for (int i = 0; i < 4; i++) pacc[i] = make_float4(0.f, 0.f, 0.f, 0.f);

    for (int base = 0; base < nk; base += 128) {
        const int csize = (nk - base < 128) ? nk - base : 128;
        __syncthreads();
#pragma unroll
        for (int i = 0; i < 8; i++) {
            int u = i * 256 + tid;
            int row = u >> 4, cu = (u & 15) << 2;
            if (row < csize) {
                float4 v = *(const float4*)(V + (bT + jlo + base + row) * D_ +
                                            h * HD_ + cu);
                *(float4*)&smf[row * VSS + (cu ^ SWZ(row))] = v;
            }
        }
        __syncthreads();
        const int half = csize >> 1;
        const int j0 = hf * half, j1 = j0 + half;
        for (int jj = j0; jj < j1; jj += 4) {
            const int swv = SWZ(jj);
            float4 wv[4], vv[4];
#pragma unroll
            for (int i = 0; i < 4; i++)
                wv[i] = *(const float4*)&Sc[(4 * pg + i) * SCS2 + base + jj];
#pragma unroll
            for (int r = 0; r < 4; r++)
                vv[r] = *(const float4*)&smf[(jj + r) * VSS + (dof ^ swv)];
#pragma unroll
            for (int i = 0; i < 4; i++) {
                pacc[i].x += wv[i].x * vv[0].x + wv[i].y * vv[1].x +
                             wv[i].z * vv[2].x + wv[i].w * vv[3].x;
                pacc[i].y += wv[i].x * vv[0].y + wv[i].y * vv[1].y +
                             wv[i].z * vv[2].y + wv[i].w * vv[3].y;
                pacc[i].z += wv[i].x * vv[0].z + wv[i].y * vv[1].z +
                             wv[i].z * vv[2].z + wv[i].w * vv[3].z;
                pacc[i].w += wv[i].x * vv[0].w + wv[i].y * vv[1].w +
                             wv[i].z * vv[2].w + wv[i].w * vv[3].w;
            }
        }
    }
    __syncthreads();

    // ---- reduce halves via union staging, write P3 hi|hi|lo
    if (hf == 0) {
#pragma unroll
        for (int i = 0; i < 4; i++)
            *(float4*)&smf[(4 * pg + i) * VSS + (dof ^ swp)] = pacc[i];
    }
    __syncthreads();
    if (hf == 1) {
#pragma unroll
        for (int i = 0; i < 4; i++) {
            float4 o = *(const float4*)&smf[(4 * pg + i) * VSS + (dof ^ swp)];
            float4 v = make_float4(pacc[i].x + o.x, pacc[i].y + o.y,
                                   pacc[i].z + o.z, pacc[i].w + o.w);
            __nv_bfloat162 hA = __floats2bfloat162_rn(v.x, v.y);
            __nv_bfloat162 hB = __floats2bfloat162_rn(v.z, v.w);
            __nv_bfloat162 lA = __floats2bfloat162_rn(v.x - __bfloat162float(hA.x),
                                                      v.y - __bfloat162float(hA.y));
            __nv_bfloat162 lB = __floats2bfloat162_rn(v.z - __bfloat162float(hB.x),
                                                      v.w - __bfloat162float(hB.y));
            uint2 hw = make_uint2(*(uint32_t*)&hA, *(uint32_t*)&hB);
            uint2 lw = make_uint2(*(uint32_t*)&lA, *(uint32_t*)&lB);
            __nv_bfloat16* p = P3 + (bT + q0 + 4 * pg + i) * KE + h * HD_ + dof;
            *(uint2*)(p)        = hw;
            *(uint2*)(p + 1024) = hw;
            *(uint2*)(p + 2048) = lw;
        }
    }
}

// ---------------------------------------------------------------------------
extern "C" void kernel_launch(void* const* d_in, const int* in_sizes, int n_in,
                              void* d_out, int out_size) {
    const float* x  = (const float*)d_in[0];
    const float* Wq = (const float*)d_in[1];
    const float* bq = (const float*)d_in[2];
    const float* Wk = (const float*)d_in[3];
    const float* bk = (const float*)d_in[4];
    const float* Wv = (const float*)d_in[5];
    const float* bv = (const float*)d_in[6];
    const float* Wo = (const float*)d_in[7];
    const float* bo = (const float*)d_in[8];
    float* out = (float*)d_out;

    const int has_attn = ((size_t)out_size >= OUT_ELEMS + ATTN_ELEMS) ? 1 : 0;

    float *pQ, *pK, *pV;
    __nv_bfloat16 *pA3, *pP3, *pW3;
    cudaGetSymbolAddress((void**)&pQ, g_Q);
    cudaGetSymbolAddress((void**)&pK, g_K);
    cudaGetSymbolAddress((void**)&pV, g_V);
    cudaGetSymbolAddress((void**)&pA3, g_A3);
    cudaGetSymbolAddress((void**)&pP3, g_P3);
    cudaGetSymbolAddress((void**)&pW3, g_W3);

    cudaFuncSetAttribute(gemm_hmma, cudaFuncAttributeMaxDynamicSharedMemorySize,
                         GSMEM);
    cudaFuncSetAttribute(attn6, cudaFuncAttributeMaxDynamicSharedMemorySize,
                         ASMEM6);

    const int nA4 = MROWS * D_ / 4;
    const int nW4 = D_ * D_ / 4;
    cvt3v<<<(nA4 + 255) / 256, 256>>>(x, pA3, nA4, 4);        // [h|h|l]
    dim3 wg((nW4 + 255) / 256, 4);
    cvtW<<<wg, 256>>>(Wq, Wk, Wv, Wo, pW3, nW4);              // [h|l|h] x4

    dim3 gqkv(3 * D_ / 128, MROWS / 128);   // (24, 32)
    gemm_hmma<<<gqkv, 128, GSMEM>>>(pA3, pW3, bq, bk, bv, pQ, pK, pV);

    dim3 agrid(T_ / 32, H_, B_);            // (64, 16, 2)
    attn6<<<agrid, 256, ASMEM6>>>(pQ, pK, pV, pP3,
                                  has_attn ? (out + OUT_ELEMS) : out, has_attn);

    dim3 go(D_ / 128, MROWS / 128);         // (8, 32)
    gemm_hmma<<<go, 128, GSMEM>>>(pP3, pW3 + 3 * (size_t)D_ * KE,
                                  bo, bo, bo, out, out, out);
}

// round 17
// speedup vs baseline: 1.0878x; 1.0135x over previous
#include <cuda_runtime.h>
#include <cuda_bf16.h>
#include <math.h>
#include <stdint.h>

// ---------------------------------------------------------------------------
// ALiBi self-attention. B=2, T=2048, D=1024, H=16, hd=64.
// sm_100 baseline: mma.sync m16n8k16 bf16 + ldmatrix + cp.async.
//  * GEMMs: R10/R15 config (128x128 CTA, 64x64 warp tiles, 3-stage, 2 CTA/SM).
//  * attn7: BOTH QK and PV on the tensor pipe (bf16 hi/lo 3-term splits).
//    PV uses ldmatrix.trans so V stays in natural [key][d] layout.
//    P->P3 hi|hi|lo written directly from mma fragments.
// ---------------------------------------------------------------------------

#define B_    2
#define T_    2048
#define D_    1024
#define H_    16
#define HD_   64
#define MROWS 4096
#define KE    3072
#define NCH   48
#define OUT_ELEMS  ((size_t)MROWS * D_)
#define ATTN_ELEMS ((size_t)B_ * H_ * T_ * T_)
#define WBACK 192

// ---------------- device scratch (allocation-free rule) --------------------
__device__ __align__(256) float g_Q[MROWS * D_];
__device__ __align__(256) float g_K[MROWS * D_];
__device__ __align__(256) float g_V[MROWS * D_];
__device__ __align__(256) __nv_bfloat16 g_A3[(size_t)MROWS * KE];
__device__ __align__(256) __nv_bfloat16 g_P3[(size_t)MROWS * KE];
__device__ __align__(256) __nv_bfloat16 g_W3[4][(size_t)D_ * KE];

// ---------------- PTX helpers ----------------------------------------------
__device__ __forceinline__ uint32_t s2u(const void* p) {
    uint32_t a;
    asm("{ .reg .u64 t; cvta.to.shared.u64 t, %1; cvt.u32.u64 %0, t; }"
        : "=r"(a) : "l"(p));
    return a;
}
__device__ __forceinline__ void cp16(uint32_t dst, const void* src) {
    asm volatile("cp.async.cg.shared.global [%0], [%1], 16;"
                 :: "r"(dst), "l"(src) : "memory");
}
#define CP_COMMIT() asm volatile("cp.async.commit_group;" ::: "memory")
#define CP_WAIT(n)  asm volatile("cp.async.wait_group %0;" :: "n"(n) : "memory")

__device__ __forceinline__ void ldsm4(uint32_t* r, uint32_t addr) {
    asm volatile("ldmatrix.sync.aligned.m8n8.x4.shared.b16 {%0,%1,%2,%3}, [%4];"
                 : "=r"(r[0]), "=r"(r[1]), "=r"(r[2]), "=r"(r[3]) : "r"(addr));
}
__device__ __forceinline__ void ldsm4t(uint32_t* r, uint32_t addr) {
    asm volatile("ldmatrix.sync.aligned.m8n8.x4.trans.shared.b16 {%0,%1,%2,%3}, [%4];"
                 : "=r"(r[0]), "=r"(r[1]), "=r"(r[2]), "=r"(r[3]) : "r"(addr));
}
__device__ __forceinline__ void mma16816(float* c, const uint32_t* a,
                                         uint32_t b0, uint32_t b1) {
    asm volatile(
        "mma.sync.aligned.m16n8k16.row.col.f32.bf16.bf16.f32 "
        "{%0,%1,%2,%3}, {%4,%5,%6,%7}, {%8,%9}, {%0,%1,%2,%3};"
        : "+f"(c[0]), "+f"(c[1]), "+f"(c[2]), "+f"(c[3])
        : "r"(a[0]), "r"(a[1]), "r"(a[2]), "r"(a[3]), "r"(b0), "r"(b1));
}

// ---------------------------------------------------------------------------
// hi/lo split kernels: fp32 [rows,1024] -> bf16 [rows,3072]
// ---------------------------------------------------------------------------
__device__ __forceinline__ void split_store(const float* __restrict__ in,
                                            __nv_bfloat16* __restrict__ out,
                                            int i, int loMask) {
    float4 v = ((const float4*)in)[i];
    __nv_bfloat162 h01 = __floats2bfloat162_rn(v.x, v.y);
    __nv_bfloat162 h23 = __floats2bfloat162_rn(v.z, v.w);
    __nv_bfloat162 l01 = __floats2bfloat162_rn(v.x - __bfloat162float(h01.x),
                                               v.y - __bfloat162float(h01.y));
    __nv_bfloat162 l23 = __floats2bfloat162_rn(v.z - __bfloat162float(h23.x),
                                               v.w - __bfloat162float(h23.y));
    uint32_t h0 = *(uint32_t*)&h01, h1 = *(uint32_t*)&h23;
    uint32_t l0 = *(uint32_t*)&l01, l1 = *(uint32_t*)&l23;
    int idx = i * 4;
    int r = idx >> 10, k = idx & 1023;
    uint32_t* o = (uint32_t*)(out + (size_t)r * KE + k);
    o[0]    = (loMask & 1) ? l0 : h0;  o[1]    = (loMask & 1) ? l1 : h1;
    o[512]  = (loMask & 2) ? l0 : h0;  o[513]  = (loMask & 2) ? l1 : h1;
    o[1024] = (loMask & 4) ? l0 : h0;  o[1025] = (loMask & 4) ? l1 : h1;
}

__global__ void __launch_bounds__(256) cvt3v(const float* __restrict__ in,
                                             __nv_bfloat16* __restrict__ out,
                                             int n4, int loMask) {
    int i = blockIdx.x * 256 + threadIdx.x;
    if (i < n4) split_store(in, out, i, loMask);
}

__global__ void __launch_bounds__(256) cvtW(const float* __restrict__ w0,
                                            const float* __restrict__ w1,
                                            const float* __restrict__ w2,
                                            const float* __restrict__ w3,
                                            __nv_bfloat16* __restrict__ outBase,
                                            int n4) {
    int i = blockIdx.x * 256 + threadIdx.x;
    if (i >= n4) return;
    int m = blockIdx.y;
    const float* in = (m == 0) ? w0 : (m == 1) ? w1 : (m == 2) ? w2 : w3;
    split_store(in, outBase + (size_t)m * D_ * KE, i, 2);
}

// ---------------------------------------------------------------------------
// HMMA bf16 GEMM (R10 config): CTA 128x128, 4 warps (2x2), warp tile 64x64,
// 3-stage cp.async, 128 threads, 2 CTAs/SM.
// ---------------------------------------------------------------------------
#define ROWB     144
#define TILEB    (128 * ROWB)
#define STAGEB   (2 * TILEB)          // 36864
#define GSMEM    (3 * STAGEB)         // 110592

__global__ void __launch_bounds__(128, 2) gemm_hmma(
    const __nv_bfloat16* __restrict__ A3, const __nv_bfloat16* __restrict__ B3,
    const float* __restrict__ bias0, const float* __restrict__ bias1,
    const float* __restrict__ bias2,
    float* __restrict__ out0, float* __restrict__ out1, float* __restrict__ out2) {
    extern __shared__ __align__(128) char smem[];
    const uint32_t sb = s2u(smem);
    const int tid  = threadIdx.x;
    const int lane = tid & 31;
    const int w    = tid >> 5;
    const int wm   = (w & 1) * 64;
    const int wn   = (w >> 1) * 64;
    const int bm   = blockIdx.y * 128;
    const int bn   = blockIdx.x * 128;

    const int mat = bn >> 10;
    const float* bias = (mat == 0) ? bias0 : (mat == 1) ? bias1 : bias2;
    float* C          = (mat == 0) ? out0  : (mat == 1) ? out1  : out2;
    const int cn = bn & 1023;

    float acc[4][8][4];
#pragma unroll
    for (int i = 0; i < 4; i++)
#pragma unroll
        for (int j = 0; j < 8; j++)
#pragma unroll
            for (int q = 0; q < 4; q++) acc[i][j][q] = 0.f;

    const char* gAbase = (const char*)A3 + (size_t)bm * (KE * 2);
    const char* gBbase = (const char*)B3 + (size_t)bn * (KE * 2);

#define LOAD_STAGE(c, s)                                                      \
    do {                                                                      \
        uint32_t dA = sb + (s) * STAGEB;                                      \
        uint32_t dB = dA + TILEB;                                             \
        const char* sA = gAbase + (c) * 128;                                  \
        const char* sB = gBbase + (c) * 128;                                  \
        _Pragma("unroll")                                                     \
        for (int it = 0; it < 8; it++) {                                      \
            int u = tid + it * 128;                                           \
            int r = u >> 3, q = (u & 7) << 4;                                 \
            cp16(dA + r * ROWB + q, sA + (size_t)r * (KE * 2) + q);           \
            cp16(dB + r * ROWB + q, sB + (size_t)r * (KE * 2) + q);           \
        }                                                                     \
        CP_COMMIT();                                                          \
    } while (0)

    LOAD_STAGE(0, 0);
    LOAD_STAGE(1, 1);

    for (int c = 0; c < NCH; c++) {
        const int s = c - (c / 3) * 3;            // c % 3
        if (c + 1 < NCH) CP_WAIT(1); else CP_WAIT(0);
        __syncthreads();
        if (c + 2 < NCH) {
            int s2 = (c + 2) - ((c + 2) / 3) * 3;
            LOAD_STAGE(c + 2, s2);
        }

        const uint32_t aBase = sb + s * STAGEB +
                               (wm + (lane & 15)) * ROWB + ((lane >> 4) << 4);
        const uint32_t bBase = sb + s * STAGEB + TILEB +
                               (wn + (lane & 15)) * ROWB + ((lane >> 4) << 4);
#pragma unroll
        for (int kk = 0; kk < 4; kk++) {
            uint32_t af[4][4], bf[4][4];
#pragma unroll
            for (int i = 0; i < 4; i++)
                ldsm4(af[i], aBase + i * 16 * ROWB + kk * 32);
#pragma unroll
            for (int p = 0; p < 4; p++)
                ldsm4(bf[p], bBase + p * 16 * ROWB + kk * 32);
#pragma unroll
            for (int i = 0; i < 4; i++)
#pragma unroll
                for (int j = 0; j < 8; j++)
                    mma16816(acc[i][j], af[i], bf[j >> 1][j & 1],
                             bf[j >> 1][(j & 1) + 2]);
        }
    }

    const int g = lane >> 2, tg = lane & 3;
#pragma unroll
    for (int i = 0; i < 4; i++) {
#pragma unroll
        for (int j = 0; j < 8; j++) {
            int col  = cn + wn + j * 8 + tg * 2;
            float b0 = bias[col], b1 = bias[col + 1];
            int row0 = bm + wm + i * 16 + g;
            float2 v0 = make_float2(acc[i][j][0] + b0, acc[i][j][1] + b1);
            float2 v1 = make_float2(acc[i][j][2] + b0, acc[i][j][3] + b1);
            *(float2*)&C[(size_t)row0 * D_ + col]       = v0;
            *(float2*)&C[(size_t)(row0 + 8) * D_ + col] = v1;
        }
    }
}

// ---------------------------------------------------------------------------
// attn7: QK AND PV on tensor pipe. smem (66048 B):
//   union [36864 B]:
//     QK phase: Q3 bf16 3 segs x [32 x 128B swz] (12288) @0
//               K3 bf16 3 segs x [64 x 128B swz] (24576) @12288
//     PV phase: P3 bf16 3 segs x [32 x 128B swz] (12288) @0   [ph|ph|pl]
//               V3 bf16 3 segs x [64 x 128B swz] (24576) @12288 [vh|vl|vh]
//   Sc float [32][228] @36864 (29184)
// ---------------------------------------------------------------------------
#define SCS2   228
#define SC2_OFF 36864
#define ASMEM6 (SC2_OFF + 32 * SCS2 * 4)    // 66048
#define K3_OFF 12288

__global__ void __launch_bounds__(256) attn7(
    const float* __restrict__ Q, const float* __restrict__ K,
    const float* __restrict__ V, __nv_bfloat16* __restrict__ P3,
    float* __restrict__ attn_out, int has_attn) {
    extern __shared__ __align__(128) char smc[];
    const uint32_t sb = s2u(smc);
    float* Sc = (float*)(smc + SC2_OFF);

    const int b = blockIdx.z, h = blockIdx.y;
    const int q0 = blockIdx.x * 32;
    const int tid = threadIdx.x;
    const int jlo = (q0 > WBACK) ? q0 - WBACK : 0;
    const int nk = q0 + 32 - jlo;             // mult of 32, <= 224
    const size_t bT = (size_t)b * T_;
    const int qr = tid >> 3, l8 = tid & 7;
    const int iq = q0 + qr;
    const int wid = tid >> 5, lane = tid & 31;

    // ---- Q3 convert: 32x64 fp32 -> 3 bf16 segs (h,h,l), swizzled 128B rows
#pragma unroll
    for (int i = 0; i < 2; i++) {
        int u = i * 256 + tid;
        int row = u >> 4, d4 = (u & 15) << 2;
        float4 v = *(const float4*)(Q + (bT + q0 + row) * D_ + h * HD_ + d4);
        __nv_bfloat162 hA = __floats2bfloat162_rn(v.x, v.y);
        __nv_bfloat162 hB = __floats2bfloat162_rn(v.z, v.w);
        __nv_bfloat162 lA = __floats2bfloat162_rn(v.x - __bfloat162float(hA.x),
                                                  v.y - __bfloat162float(hA.y));
        __nv_bfloat162 lB = __floats2bfloat162_rn(v.z - __bfloat162float(hB.x),
                                                  v.w - __bfloat162float(hB.y));
        uint2 hw = make_uint2(*(uint32_t*)&hA, *(uint32_t*)&hB);
        uint2 lw = make_uint2(*(uint32_t*)&lA, *(uint32_t*)&lB);
        uint32_t off = row * 128 + ((((d4 >> 3) ^ (row & 7))) << 4) + ((d4 & 4) << 1);
        *(uint2*)(smc + 0    + off) = hw;
        *(uint2*)(smc + 4096 + off) = hw;
        *(uint2*)(smc + 8192 + off) = lw;
    }

    const int mt = (wid & 1) * 16;            // m-tile (query base)
    const int ng = wid >> 1;                  // n-group (16 keys / 16 d)

    // ---- QK: keys in chunks of 64, HMMA over expanded k=192
    for (int base = 0; base < nk; base += 64) {
        const int csize = (nk - base < 64) ? nk - base : 64;   // 32 or 64
        __syncthreads();
#pragma unroll
        for (int i = 0; i < 4; i++) {         // K3 convert (h,l,h)
            int u = i * 256 + tid;
            int row = u >> 4, d4 = (u & 15) << 2;
            if (row < csize) {
                float4 v = *(const float4*)(K + (bT + jlo + base + row) * D_ +
                                            h * HD_ + d4);
                __nv_bfloat162 hA = __floats2bfloat162_rn(v.x, v.y);
                __nv_bfloat162 hB = __floats2bfloat162_rn(v.z, v.w);
                __nv_bfloat162 lA = __floats2bfloat162_rn(v.x - __bfloat162float(hA.x),
                                                          v.y - __bfloat162float(hA.y));
                __nv_bfloat162 lB = __floats2bfloat162_rn(v.z - __bfloat162float(hB.x),
                                                          v.w - __bfloat162float(hB.y));
                uint2 hw = make_uint2(*(uint32_t*)&hA, *(uint32_t*)&hB);
                uint2 lw = make_uint2(*(uint32_t*)&lA, *(uint32_t*)&lB);
                uint32_t off = row * 128 + ((((d4 >> 3) ^ (row & 7))) << 4) +
                               ((d4 & 4) << 1);
                *(uint2*)(smc + K3_OFF + 0     + off) = hw;
                *(uint2*)(smc + K3_OFF + 8192  + off) = lw;
                *(uint2*)(smc + K3_OFF + 16384 + off) = hw;
            }
        }
        __syncthreads();
        if (ng * 16 < csize) {
            float acc0[4] = {0.f, 0.f, 0.f, 0.f};
            float acc1[4] = {0.f, 0.f, 0.f, 0.f};
#pragma unroll
            for (int s = 0; s < 3; s++) {
                const uint32_t qb = sb + s * 4096;
                const uint32_t kb = sb + K3_OFF + s * 8192;
#pragma unroll
                for (int ks = 0; ks < 4; ks++) {
                    uint32_t af[4], bf[4];
                    {
                        int r = mt + (lane & 15);
                        int c = ks * 2 + (lane >> 4);
                        ldsm4(af, qb + r * 128 + ((c ^ (r & 7)) << 4));
                    }
                    {
                        int r = ng * 16 + (lane & 15);
                        int c = ks * 2 + (lane >> 4);
                        ldsm4(bf, kb + r * 128 + ((c ^ (r & 7)) << 4));
                    }
                    mma16816(acc0, af, bf[0], bf[2]);
                    mma16816(acc1, af, bf[1], bf[3]);
                }
            }
            const int g = lane >> 2, tg = lane & 3;
            const int r0 = mt + g;
            const int cb = base + ng * 16 + tg * 2;
            Sc[r0 * SCS2 + cb]           = acc0[0] * 0.125f;
            Sc[r0 * SCS2 + cb + 1]       = acc0[1] * 0.125f;
            Sc[(r0 + 8) * SCS2 + cb]     = acc0[2] * 0.125f;
            Sc[(r0 + 8) * SCS2 + cb + 1] = acc0[3] * 0.125f;
            Sc[r0 * SCS2 + cb + 8]       = acc1[0] * 0.125f;
            Sc[r0 * SCS2 + cb + 9]       = acc1[1] * 0.125f;
            Sc[(r0 + 8) * SCS2 + cb + 8] = acc1[2] * 0.125f;
            Sc[(r0 + 8) * SCS2 + cb + 9] = acc1[3] * 0.125f;
        }
    }
    __syncthreads();

    // ---- softmax per query row (8 lanes/row)
    float m = -1e30f;
    for (int idx = l8; idx < nk; idx += 8) {
        int j = jlo + idx;
        int ph = qr * SCS2 + idx;
        float sv = (j <= iq) ? (Sc[ph] - (float)(iq - j)) : -1e30f;
        Sc[ph] = sv;
        m = fmaxf(m, sv);
    }
#pragma unroll
    for (int o = 4; o >= 1; o >>= 1)
        m = fmaxf(m, __shfl_xor_sync(0xffffffffu, m, o, 8));
    float sum = 0.f;
    for (int idx = l8; idx < nk; idx += 8) {
        int ph = qr * SCS2 + idx;
        float sv = Sc[ph];
        float e = (sv > -1e29f) ? expf(sv - m) : 0.f;
        Sc[ph] = e;
        sum += e;
    }
#pragma unroll
    for (int o = 4; o >= 1; o >>= 1)
        sum += __shfl_xor_sync(0xffffffffu, sum, o, 8);
    float inv = 1.f / sum;
    for (int idx = l8; idx < nk; idx += 8)
        Sc[qr * SCS2 + idx] *= inv;
    __syncthreads();

    // ---- full attn row (float4, zeros outside band)
    if (has_attn) {
        float* row = attn_out + ((size_t)(b * H_ + h) * T_ + iq) * T_;
        for (int j4 = l8; j4 < T_ / 4; j4 += 8) {
            int j = j4 * 4;
            float4 v = make_float4(0.f, 0.f, 0.f, 0.f);
            if (j + 3 >= jlo && j <= iq) {
                int lo0 = j - jlo;
                v.x = (j + 0 >= jlo && j + 0 <= iq) ? Sc[qr * SCS2 + lo0 + 0] : 0.f;
                v.y = (j + 1 >= jlo && j + 1 <= iq) ? Sc[qr * SCS2 + lo0 + 1] : 0.f;
                v.z = (j + 2 >= jlo && j + 2 <= iq) ? Sc[qr * SCS2 + lo0 + 2] : 0.f;
                v.w = (j + 3 >= jlo && j + 3 <= iq) ? Sc[qr * SCS2 + lo0 + 3] : 0.f;
            }
            *(float4*)(row + j) = v;
        }
    }

    // ---- PV on tensor pipe: chunks of 64 keys, k expanded to 192.
    //      P3 segs (h,h,l) @0; V3 segs (h,l,h) @K3_OFF. acc persists.
    float pac0[4] = {0.f, 0.f, 0.f, 0.f};     // d = ng*16 + 0..7
    float pac1[4] = {0.f, 0.f, 0.f, 0.f};     // d = ng*16 + 8..15

    for (int base = 0; base < nk; base += 64) {
        const int csize = (nk - base < 64) ? nk - base : 64;
        __syncthreads();
        // P3 convert: rows q (32) x 64 j-cols; zero beyond csize
#pragma unroll
        for (int i = 0; i < 2; i++) {
            int u = i * 256 + tid;
            int row = u >> 4, j4 = (u & 15) << 2;
            uint2 hw = make_uint2(0u, 0u), lw = make_uint2(0u, 0u);
            if (j4 < csize) {
                float4 v = *(const float4*)&Sc[row * SCS2 + base + j4];
                __nv_bfloat162 hA = __floats2bfloat162_rn(v.x, v.y);
                __nv_bfloat162 hB = __floats2bfloat162_rn(v.z, v.w);
                __nv_bfloat162 lA = __floats2bfloat162_rn(v.x - __bfloat162float(hA.x),
                                                          v.y - __bfloat162float(hA.y));
                __nv_bfloat162 lB = __floats2bfloat162_rn(v.z - __bfloat162float(hB.x),
                                                          v.w - __bfloat162float(hB.y));
                hw = make_uint2(*(uint32_t*)&hA, *(uint32_t*)&hB);
                lw = make_uint2(*(uint32_t*)&lA, *(uint32_t*)&lB);
            }
            uint32_t off = row * 128 + ((((j4 >> 3) ^ (row & 7))) << 4) + ((j4 & 4) << 1);
            *(uint2*)(smc + 0    + off) = hw;
            *(uint2*)(smc + 4096 + off) = hw;
            *(uint2*)(smc + 8192 + off) = lw;
        }
        // V3 convert: rows j (64) x 64 d-cols, natural layout; zero rows >= csize
#pragma unroll
        for (int i = 0; i < 4; i++) {
            int u = i * 256 + tid;
            int row = u >> 4, d4 = (u & 15) << 2;
            uint2 hw = make_uint2(0u, 0u), lw = make_uint2(0u, 0u);
            if (row < csize) {
                float4 v = *(const float4*)(V + (bT + jlo + base + row) * D_ +
                                            h * HD_ + d4);
                __nv_bfloat162 hA = __floats2bfloat162_rn(v.x, v.y);
                __nv_bfloat162 hB = __floats2bfloat162_rn(v.z, v.w);
                __nv_bfloat162 lA = __floats2bfloat162_rn(v.x - __bfloat162float(hA.x),
                                                          v.y - __bfloat162float(hA.y));
                __nv_bfloat162 lB = __floats2bfloat162_rn(v.z - __bfloat162float(hB.x),
                                                          v.w - __bfloat162float(hB.y));
                hw = make_uint2(*(uint32_t*)&hA, *(uint32_t*)&hB);
                lw = make_uint2(*(uint32_t*)&lA, *(uint32_t*)&lB);
            }
            uint32_t off = row * 128 + ((((d4 >> 3) ^ (row & 7))) << 4) + ((d4 & 4) << 1);
            *(uint2*)(smc + K3_OFF + 0     + off) = hw;
            *(uint2*)(smc + K3_OFF + 8192  + off) = lw;
            *(uint2*)(smc + K3_OFF + 16384 + off) = hw;
        }
        __syncthreads();
#pragma unroll
        for (int s = 0; s < 3; s++) {
            const uint32_t pb = sb + s * 4096;
            const uint32_t vb = sb + K3_OFF + s * 8192;
#pragma unroll
            for (int ks = 0; ks < 4; ks++) {
                uint32_t af[4], bf[4];
                {   // A: P3 [q rows][j cols], non-trans
                    int r = mt + (lane & 15);
                    int c = ks * 2 + (lane >> 4);
                    ldsm4(af, pb + r * 128 + ((c ^ (r & 7)) << 4));
                }
                {   // B: V3 [j rows][d cols], TRANS -> (d x j) fragments
                    int r = ks * 16 + (lane & 15);
                    int c = ng * 2 + (lane >> 4);
                    ldsm4t(bf, vb + r * 128 + ((c ^ (r & 7)) << 4));
                }
                mma16816(pac0, af, bf[0], bf[1]);   // d = ng*16 + 0..7
                mma16816(pac1, af, bf[2], bf[3]);   // d = ng*16 + 8..15
            }
        }
    }

    // ---- write P3 global (hi|hi|lo) directly from fragments
    {
        const int g = lane >> 2, tg = lane & 3;
#pragma unroll
        for (int half = 0; half < 2; half++) {
            const float* a = half ? pac1 : pac0;
            const int dd = ng * 16 + half * 8 + tg * 2;
#pragma unroll
            for (int rr = 0; rr < 2; rr++) {
                float x = a[rr * 2], y = a[rr * 2 + 1];
                __nv_bfloat162 hh = __floats2bfloat162_rn(x, y);
                __nv_bfloat162 ll = __floats2bfloat162_rn(
                    x - __bfloat162float(hh.x), y - __bfloat162float(hh.y));
                uint32_t hwv = *(uint32_t*)&hh, lwv = *(uint32_t*)&ll;
                int row = mt + g + rr * 8;
                __nv_bfloat16* p = P3 + (bT + q0 + row) * KE + h * HD_ + dd;
                *(uint32_t*)(p)        = hwv;
                *(uint32_t*)(p + 1024) = hwv;
                *(uint32_t*)(p + 2048) = lwv;
            }
        }
    }
}

// ---------------------------------------------------------------------------
extern "C" void kernel_launch(void* const* d_in, const int* in_sizes, int n_in,
                              void* d_out, int out_size) {
    const float* x  = (const float*)d_in[0];
    const float* Wq = (const float*)d_in[1];
    const float* bq = (const float*)d_in[2];
    const float* Wk = (const float*)d_in[3];
    const float* bk = (const float*)d_in[4];
    const float* Wv = (const float*)d_in[5];
    const float* bv = (const float*)d_in[6];
    const float* Wo = (const float*)d_in[7];
    const float* bo = (const float*)d_in[8];
    float* out = (float*)d_out;

    const int has_attn = ((size_t)out_size >= OUT_ELEMS + ATTN_ELEMS) ? 1 : 0;

    float *pQ, *pK, *pV;
    __nv_bfloat16 *pA3, *pP3, *pW3;
    cudaGetSymbolAddress((void**)&pQ, g_Q);
    cudaGetSymbolAddress((void**)&pK, g_K);
    cudaGetSymbolAddress((void**)&pV, g_V);
    cudaGetSymbolAddress((void**)&pA3, g_A3);
    cudaGetSymbolAddress((void**)&pP3, g_P3);
    cudaGetSymbolAddress((void**)&pW3, g_W3);

    cudaFuncSetAttribute(gemm_hmma, cudaFuncAttributeMaxDynamicSharedMemorySize,
                         GSMEM);
    cudaFuncSetAttribute(attn7, cudaFuncAttributeMaxDynamicSharedMemorySize,
                         ASMEM6);

    const int nA4 = MROWS * D_ / 4;
    const int nW4 = D_ * D_ / 4;
    cvt3v<<<(nA4 + 255) / 256, 256>>>(x, pA3, nA4, 4);        // [h|h|l]
    dim3 wg((nW4 + 255) / 256, 4);
    cvtW<<<wg, 256>>>(Wq, Wk, Wv, Wo, pW3, nW4);              // [h|l|h] x4

    dim3 gqkv(3 * D_ / 128, MROWS / 128);   // (24, 32)
    gemm_hmma<<<gqkv, 128, GSMEM>>>(pA3, pW3, bq, bk, bv, pQ, pK, pV);

    dim3 agrid(T_ / 32, H_, B_);            // (64, 16, 2)
    attn7<<<agrid, 256, ASMEM6>>>(pQ, pK, pV, pP3,
                                  has_attn ? (out + OUT_ELEMS) : out, has_attn);

    dim3 go(D_ / 128, MROWS / 128);         // (8, 32)
    gemm_hmma<<<go, 128, GSMEM>>>(pP3, pW3 + 3 * (size_t)D_ * KE,
                                  bo, bo, bo, out, out, out);
}